// round 3
// baseline (speedup 1.0000x reference)
#include <cuda_runtime.h>
#include <math.h>

// Problem constants (fixed by the dataset): B=256, K=512, D=1024
#define B_SZ 256
#define K_SZ 512
#define D_SZ 1024
#define INV_T (1.0f / 0.07f)

#define K_PER_BLOCK 8                      // 8 warps per block, one k per warp
#define BLOCKS_PER_B (K_SZ / K_PER_BLOCK)  // 64
#define NBLK (B_SZ * BLOCKS_PER_B)         // 16384

// Scratch (no cudaMalloc allowed)
__device__ float g_fg_per_b[B_SZ];       // exp(fg_logit / T) per sample
__device__ float g_part[NBLK];           // per-block partial sums of exp(bg_logit/T)

// ---------------------------------------------------------------------------
// Fused kernel: per-block img-row normalization (redundant 64x per row, L2
// hits) + 8 warps each streaming one pro row from DRAM and dotting against
// the smem-resident img row. kgrp==0 blocks additionally compute the fg dot.
// grid = 16384, block = 256 (8 warps)
// ---------------------------------------------------------------------------
__global__ void __launch_bounds__(256) fused_kernel(
    const float* __restrict__ img,
    const float* __restrict__ fg,
    const float* __restrict__ pro)
{
    __shared__ float4 s_img[256];   // 4 KB: the img row, float4 per thread
    __shared__ float  s_ss[8];
    __shared__ float  s_fg[8];
    __shared__ float  s_part[8];

    const int blk  = blockIdx.x;
    const int b    = blk >> 6;          // blk / BLOCKS_PER_B
    const int kgrp = blk & 63;          // blk % BLOCKS_PER_B
    const int t    = threadIdx.x;
    const int w    = t >> 5;
    const int l    = t & 31;

    // ---- load img row into smem + sum of squares ----
    float4 v = ((const float4*)(img + (size_t)b * D_SZ))[t];
    s_img[t] = v;

    float ss = v.x * v.x + v.y * v.y + v.z * v.z + v.w * v.w;
    #pragma unroll
    for (int o = 16; o > 0; o >>= 1)
        ss += __shfl_xor_sync(0xFFFFFFFFu, ss, o);
    if (l == 0) s_ss[w] = ss;
    __syncthreads();

    float tss = 0.f;
    #pragma unroll
    for (int i = 0; i < 8; i++) tss += s_ss[i];
    const float inv = 1.0f / sqrtf(tss);

    // ---- fg dot: only in the first block of each sample (256 blocks) ----
    if (kgrp == 0) {
        float4 f = ((const float4*)(fg + (size_t)b * D_SZ))[t];
        float fd = v.x * f.x + v.y * f.y + v.z * f.z + v.w * f.w;
        #pragma unroll
        for (int o = 16; o > 0; o >>= 1)
            fd += __shfl_xor_sync(0xFFFFFFFFu, fd, o);
        if (l == 0) s_fg[w] = fd;
        __syncthreads();
        if (t == 0) {
            float tfd = 0.f;
            #pragma unroll
            for (int i = 0; i < 8; i++) tfd += s_fg[i];
            g_fg_per_b[b] = expf(tfd * inv * INV_T);
        }
    }

    // ---- each warp: one (b,k) dot, pro streamed from DRAM ----
    const int k = (kgrp << 3) + w;
    const float4* p4 = (const float4*)(pro + ((size_t)b * K_SZ + k) * D_SZ);

    // front-batch the 8 independent streaming loads for max MLP
    float4 p[8];
    #pragma unroll
    for (int j = 0; j < 8; j++)
        p[j] = __ldcs(p4 + j * 32 + l);

    float acc = 0.f;
    #pragma unroll
    for (int j = 0; j < 8; j++) {
        float4 a = s_img[j * 32 + l];
        acc += a.x * p[j].x + a.y * p[j].y + a.z * p[j].z + a.w * p[j].w;
    }

    #pragma unroll
    for (int o = 16; o > 0; o >>= 1)
        acc += __shfl_xor_sync(0xFFFFFFFFu, acc, o);
    if (l == 0) s_part[w] = expf(acc * inv * INV_T);
    __syncthreads();

    if (t == 0) {
        float tsum = 0.f;
        #pragma unroll
        for (int i = 0; i < 8; i++) tsum += s_part[i];
        g_part[blk] = tsum;   // fixed order: deterministic across replays
    }
}

// ---------------------------------------------------------------------------
// Final deterministic reduce, wide version: 1024 threads, float4 loads.
// 16384 partials = 4096 float4 -> 4 independent vec loads per thread
// (front-batched, one memory round-trip). fg terms by first 256 threads.
// grid = 1, block = 1024
// ---------------------------------------------------------------------------
__global__ void __launch_bounds__(1024) reduce_kernel(float* __restrict__ out)
{
    const int t = threadIdx.x;
    const int w = t >> 5;
    const int l = t & 31;

    // ---- front-batched independent loads ----
    const float4* gp4 = (const float4*)g_part;
    float4 v0 = gp4[t];
    float4 v1 = gp4[t + 1024];
    float4 v2 = gp4[t + 2048];
    float4 v3 = gp4[t + 3072];
    float fgv = (t < B_SZ) ? g_fg_per_b[t] : 0.0f;

    double acc = ((double)v0.x + (double)v0.y) + ((double)v0.z + (double)v0.w)
               + ((double)v1.x + (double)v1.y) + ((double)v1.z + (double)v1.w)
               + ((double)v2.x + (double)v2.y) + ((double)v2.z + (double)v2.w)
               + ((double)v3.x + (double)v3.y) + ((double)v3.z + (double)v3.w);
    double fgd = (double)fgv;

    // ---- warp-level tree (deterministic: fixed lane order) ----
    #pragma unroll
    for (int o = 16; o > 0; o >>= 1) {
        acc += __shfl_xor_sync(0xFFFFFFFFu, acc, o);
        fgd += __shfl_xor_sync(0xFFFFFFFFu, fgd, o);
    }

    __shared__ double sa[32];
    __shared__ double sf[32];
    if (l == 0) { sa[w] = acc; sf[w] = fgd; }
    __syncthreads();

    if (w == 0) {
        double a = sa[l];
        double f = sf[l];
        #pragma unroll
        for (int o = 16; o > 0; o >>= 1) {
            a += __shfl_xor_sync(0xFFFFFFFFu, a, o);
            f += __shfl_xor_sync(0xFFFFFFFFu, f, o);
        }
        if (l == 0) {
            double pos = a / (double)K_SZ;   // sum_b mean_k exp(...)
            double neg = pos + f;
            out[0] = (float)(-log(pos / neg));
        }
    }
}

// ---------------------------------------------------------------------------
extern "C" void kernel_launch(void* const* d_in, const int* in_sizes, int n_in,
                              void* d_out, int out_size)
{
    const float* img = (const float*)d_in[0];  // bg_img_feature [256,1024]
    const float* fg  = (const float*)d_in[1];  // fg_pro_feature [256,1024]
    const float* pro = (const float*)d_in[2];  // bg_pro_feature [256,512,1024]

    fused_kernel<<<NBLK, 256>>>(img, fg, pro);
    reduce_kernel<<<1, 1024>>>((float*)d_out);
}